// round 15
// baseline (speedup 1.0000x reference)
#include <cuda_runtime.h>
#include <cuda_fp16.h>

#define TN 400
#define PN 4000
#define NBLOCKS 152       // one block per GB300 SM
#define TPB 832           // 26 warps = 2 groups x 13 warps (416 thr, 400 targets)
#define GW  416
#define MAXP 28           // >= ceil(PN/NBLOCKS)+1
#define ROW 32            // 32-bit slots per pred row (power of 2)

// dynamic smem layout (floats):
//   stg  [0 .. 21200)           staged tkp (400 x 53), fp32
//   sraw [21200 .. 22688)       staged raw pred rows (<=28 x 53)
//   ptile[22688 .. +MAXP*ROW)   preprocessed pred rows
#define STG_OFF   0
#define SRAW_OFF  21200
#define PTILE_OFF 22688
#define SMEM_FLOATS (PTILE_OFF + MAXP * ROW)
#define SMEM_BYTES  (SMEM_FLOATS * 4)

// pred row (32 x 32-bit slots):
//   u[0..16]  half2 {x,y} of kp0..16
//   u[17]     half2 {cp0, cp1}
//   u[18]     fp32 bits: p0-p1
//   u[19]     fp32 bits: spp  (= 0.2/nb*|Vp|^2 + 0.5/nb*|Cp|^2 - p0)
//   u[20..28] half2 Vp pairs {(0,1),(2,3),...,(14,15),(16,0)}
//   u[29..31] 0

__device__ __forceinline__ __half2 u2h(unsigned u) {
    __half2 h; *reinterpret_cast<unsigned*>(&h) = u; return h;
}
__device__ __forceinline__ unsigned h2u(__half2 h) {
    return *reinterpret_cast<unsigned*>(&h);
}

__global__ __launch_bounds__(TPB, 1)
void matcher_kernel(const float* __restrict__ logits,   // [PN,2]
                    const float* __restrict__ pkp,      // [PN,53]
                    const int*   __restrict__ tids,     // [TN]
                    const float* __restrict__ tkp,      // [TN,53]
                    const int*   __restrict__ nbp,      // scalar num_boxes
                    float*       __restrict__ out)      // [PN,TN]
{
    extern __shared__ __align__(16) float dsm[];
    float* stg   = dsm + STG_OFF;
    float* sraw  = dsm + SRAW_OFF;
    float* ptile = dsm + PTILE_OFF;

    const int b = blockIdx.x;
    const int pbase = (b * PN) / NBLOCKS;
    const int npred = ((b + 1) * PN) / NBLOCKS - pbase;
    const int tid = threadIdx.x;
    const int g   = tid / GW;             // pred-half group 0/1
    const int ti  = tid - g * GW;         // 0..415
    const bool act = (ti < TN);
    const int tl = act ? ti : 0;

    int nbi = *nbp;
    float nb = (nbi > 0 && nbi < (1 << 20)) ? (float)nbi : *(const float*)nbp;
    const float inb = 1.0f / nb;

    // ---- coalesced staging (once per SM): targets + this block's raw preds ----
    {
        const float4* src = (const float4*)tkp;       // 21200 floats = 5300 float4
        float4* dst = (float4*)stg;
        #pragma unroll
        for (int i = 0; i < 7; ++i) {
            int idx = tid + i * TPB;
            if (idx < 5300) dst[idx] = src[idx];
        }
        const int nraw = npred * 53;
        const float* ps = pkp + pbase * 53;
        for (int i = tid; i < nraw; i += TPB) sraw[i] = ps[i];
    }
    __syncthreads();

    // ---- ptile fill (fp32 -> half2), parallel across all threads ----
    {
        const int total = npred * ROW;
        for (int idx = tid; idx < total; idx += TPB) {
            const int r = idx >> 5;
            const int s = idx & 31;
            if (s >= 17 && s < 20) continue;          // scalar slots (per-pred thread)
            const float* kp = sraw + r * 53;
            unsigned val = 0u;
            if (s < 17) {                             // kp j = s: {x, y}
                val = h2u(__floats2half2_rn(kp[2 + 2 * s], kp[3 + 2 * s]));
            } else if (s >= 20 && s < 28) {           // Vp pairs (2i, 2i+1)
                const int i = s - 20;
                val = h2u(__floats2half2_rn(kp[36 + 2 * i], kp[37 + 2 * i]));
            } else if (s == 28) {                     // (V16, 0)
                val = h2u(__floats2half2_rn(kp[52], 0.0f));
            }
            ((unsigned*)(ptile + r * ROW))[s] = val;
        }
    }
    // ---- per-pred scalars (threads 0..npred-1) ----
    if (tid < npred) {
        const int gp = pbase + tid;
        const float l0 = logits[gp * 2 + 0];
        const float l1 = logits[gp * 2 + 1];
        const float m  = fmaxf(l0, l1);
        const float e0 = __expf(l0 - m);
        const float e1 = __expf(l1 - m);
        const float inv = 1.0f / (e0 + e1);
        const float p0 = e0 * inv, p1 = e1 * inv;

        const float* kp = sraw + tid * 53;
        const float c0 = kp[0], c1 = kp[1];
        float sv = 0.0f;
        #pragma unroll
        for (int j = 0; j < 17; ++j) { float v = kp[36 + j]; sv = fmaf(v, v, sv); }
        unsigned* sp = (unsigned*)(ptile + tid * ROW);
        sp[17] = h2u(__floats2half2_rn(c0, c1));
        sp[18] = __float_as_uint(p0 - p1);
        sp[19] = __float_as_uint(
            0.2f * inb * sv + 0.5f * inb * (c0 * c0 + c1 * c1) - p0);  // spp
    }

    // ---- per-thread target state: all 17 keypoints (half2) ----
    const float* tk = stg + tl * 53;
    const float cg0 = tk[0], cg1 = tk[1];
    __half2 nzg[17];           // {-Zg_x, -Zg_y} per kp
    __half2 w2[17];            // {0.5*inb*Vg, same}
    __half2 wv2[9];            // viz pairs {-0.8*w_2i, -0.8*w_2i+1}
    float wj[17];
    #pragma unroll
    for (int j = 0; j < 17; ++j) {
        nzg[j] = __floats2half2_rn(-tk[2 + 2 * j], -tk[3 + 2 * j]);
        wj[j]  = 0.5f * inb * tk[36 + j];
        w2[j]  = __half2half2(__float2half_rn(wj[j]));
    }
    #pragma unroll
    for (int i = 0; i < 8; ++i)
        wv2[i] = __floats2half2_rn(-0.8f * wj[2 * i], -0.8f * wj[2 * i + 1]);
    wv2[8] = __floats2half2_rn(-0.8f * wj[16], 0.0f);
    const __half2 eight2 = __half2half2(__float2half_rn(8.0f));
    const __half2 ncg2 = __floats2half2_rn(-cg0, -cg1);
    const __half2 tc2  = __floats2half2_rn(-inb * cg0, -inb * cg1);  // center cross
    float sv = 0.0f;
    #pragma unroll
    for (int j = 0; j < 17; ++j) { float v = tk[36 + j]; sv = fmaf(v, v, sv); }
    const float sgt = 0.2f * inb * sv + 0.5f * inb * (cg0 * cg0 + cg1 * cg1);
    const float idf = (float)tids[tl];
    __syncthreads();

    auto compute = [&](const float* pp) -> float {
        const unsigned* ru = (const unsigned*)pp;
        const uint4 zc = *(const uint4*)(ru + 16);     // {z16, cp2, p0-p1, spp}
        const __half2 dc = __hadd2(u2h(zc.y), ncg2);   // Cp - Cg (half2)

        const uint4 z0 = *(const uint4*)(ru);          // kp 0..3
        const uint4 z1 = *(const uint4*)(ru + 4);      // kp 4..7
        const uint4 z2 = *(const uint4*)(ru + 8);      // kp 8..11
        const uint4 z3 = *(const uint4*)(ru + 12);     // kp 12..15

        __half2 acc0 = __floats2half2_rn(0.0f, 0.0f);
        __half2 acc1 = __floats2half2_rn(0.0f, 0.0f);
        #define KP(zr, i, A) do {                                          \
            __half2 z  = u2h(zr);                                          \
            __half2 dz = __hadd2(z, nzg[i]);                               \
            __half2 t  = __hadd2(dz, dc);                                  \
            __half2 c  = __hfma2(__habs2(t), eight2, __habs2(dz));         \
            A = __hfma2(c, w2[i], A);                                      \
        } while (0)
        KP(z0.x,  0, acc0); KP(z0.y,  1, acc1); KP(z0.z,  2, acc0); KP(z0.w,  3, acc1);
        KP(z1.x,  4, acc0); KP(z1.y,  5, acc1); KP(z1.z,  6, acc0); KP(z1.w,  7, acc1);
        KP(z2.x,  8, acc0); KP(z2.y,  9, acc1); KP(z2.z, 10, acc0); KP(z2.w, 11, acc1);
        KP(z3.x, 12, acc0); KP(z3.y, 13, acc1); KP(z3.z, 14, acc0); KP(z3.w, 15, acc1);
        KP(zc.x, 16, acc0);
        #undef KP

        // viz dot (half2 pairs, -0.8 premultiplied into wv2)
        const uint4 vA = *(const uint4*)(ru + 20);
        const uint4 vB = *(const uint4*)(ru + 24);
        const unsigned v16 = ru[28];
        __half2 dv2 = __hmul2(u2h(vA.x), wv2[0]);
        dv2 = __hfma2(u2h(vA.y), wv2[1], dv2);
        dv2 = __hfma2(u2h(vA.z), wv2[2], dv2);
        dv2 = __hfma2(u2h(vA.w), wv2[3], dv2);
        dv2 = __hfma2(u2h(vB.x), wv2[4], dv2);
        dv2 = __hfma2(u2h(vB.y), wv2[5], dv2);
        dv2 = __hfma2(u2h(vB.z), wv2[6], dv2);
        dv2 = __hfma2(u2h(vB.w), wv2[7], dv2);
        dv2 = __hfma2(u2h(v16),  wv2[8], dv2);

        // center-cross in half (small magnitudes), fold into accumulator tree
        __half2 epi = __hmul2(u2h(zc.y), tc2);         // {tcx*cp0, tcy*cp1}
        __half2 rh  = __hadd2(__hadd2(acc0, acc1), __hadd2(dv2, epi));
        const float2 rf = __half22float2(rh);

        // large-magnitude terms in fp32: class + softmax constants
        float res = rf.x + rf.y;
        res = fmaf(__uint_as_float(zc.z), idf, res);   // id * (p0-p1)
        return res + __uint_as_float(zc.w) + sgt;      // spp + target const
    };

    // ---- pred range for this group ----
    const int nh  = (npred + 1) >> 1;
    const int pLo = g ? nh : 0;
    const int pHi = g ? npred : nh;

    int p = pLo;
    for (; p + 1 < pHi; p += 2) {
        float r0 = compute(ptile + p * ROW);
        float r1 = compute(ptile + (p + 1) * ROW);
        if (act) {
            float* o = out + (size_t)(pbase + p) * TN + tl;
            o[0]  = r0;
            o[TN] = r1;
        }
    }
    if (p < pHi) {
        float r0 = compute(ptile + p * ROW);
        if (act)
            out[(size_t)(pbase + p) * TN + tl] = r0;
    }
}

extern "C" void kernel_launch(void* const* d_in, const int* in_sizes, int n_in,
                              void* d_out, int out_size)
{
    const float* logits = (const float*)d_in[0];   // pred_logits   [8,500,2]
    const float* pkp    = (const float*)d_in[1];   // pred_keypoints[8,500,53]
    const int*   tids   = (const int*)  d_in[2];   // tgt_ids       [400]
    const float* tkp    = (const float*)d_in[3];   // tgt_keypoints [400,53]
    const int*   nbp    = (const int*)  d_in[4];   // num_boxes scalar
    (void)in_sizes; (void)n_in; (void)out_size;

    static int smem_set = 0;
    if (!smem_set) {
        cudaFuncSetAttribute(matcher_kernel,
                             cudaFuncAttributeMaxDynamicSharedMemorySize, SMEM_BYTES);
        smem_set = 1;
    }
    matcher_kernel<<<NBLOCKS, TPB, SMEM_BYTES>>>(logits, pkp, tids, tkp, nbp,
                                                 (float*)d_out);
}